// round 16
// baseline (speedup 1.0000x reference)
#include <cuda_runtime.h>
#include <cuda_fp16.h>
#include <cstdint>

// Problem constants (fixed by the dataset)
#define BB    2
#define SS    1024
#define NBLK  64
#define DIM   256
#define NH    8
#define DHD   32
#define NROWS (BB * SS * NBLK)   // 131072

// ---------------------------------------------------------------------------
// Scratch (allocation-free rule: __device__ globals).
// Projected Q/K/V stored as fp16 hi/lo pairs.
// ---------------------------------------------------------------------------
__device__ __half g_Qh[NROWS * DIM];
__device__ __half g_Ql[NROWS * DIM];
__device__ __half g_Kh[NROWS * DIM];
__device__ __half g_Kl[NROWS * DIM];
__device__ __half g_Vh[NROWS * DIM];
__device__ __half g_Vl[NROWS * DIM];
__device__ __half g_Whi[3][DIM * DIM];
__device__ __half g_Wlo[3][DIM * DIM];

// ---------------------------------------------------------------------------
// Helpers
// ---------------------------------------------------------------------------
__device__ __forceinline__ uint32_t smem_u32(const void* p) {
    uint32_t a;
    asm("{ .reg .u64 t; cvta.to.shared.u64 t, %1; cvt.u32.u64 %0, t; }"
        : "=r"(a) : "l"(p));
    return a;
}
__device__ __forceinline__ void ldmx4(uint32_t* r, uint32_t addr) {
    asm volatile("ldmatrix.sync.aligned.m8n8.x4.shared.b16 {%0,%1,%2,%3}, [%4];"
                 : "=r"(r[0]), "=r"(r[1]), "=r"(r[2]), "=r"(r[3]) : "r"(addr));
}
__device__ __forceinline__ void ldmx4t(uint32_t* r, uint32_t addr) {
    asm volatile("ldmatrix.sync.aligned.m8n8.x4.trans.shared.b16 {%0,%1,%2,%3}, [%4];"
                 : "=r"(r[0]), "=r"(r[1]), "=r"(r[2]), "=r"(r[3]) : "r"(addr));
}
// fp16 MMA, fp32 accumulate
__device__ __forceinline__ void mma16816(float* d, const uint32_t* a,
                                         uint32_t b0, uint32_t b1) {
    asm volatile("mma.sync.aligned.m16n8k16.row.col.f32.f16.f16.f32 "
                 "{%0,%1,%2,%3}, {%4,%5,%6,%7}, {%8,%9}, {%0,%1,%2,%3};"
                 : "+f"(d[0]), "+f"(d[1]), "+f"(d[2]), "+f"(d[3])
                 : "r"(a[0]), "r"(a[1]), "r"(a[2]), "r"(a[3]), "r"(b0), "r"(b1));
}
__device__ __forceinline__ void cpasync16(uint32_t saddr, const void* gptr) {
    asm volatile("cp.async.cg.shared.global [%0], [%1], 16;"
                 :: "r"(saddr), "l"(gptr) : "memory");
}
#define CP_COMMIT() asm volatile("cp.async.commit_group;" ::: "memory")
#define CP_WAIT(n)  asm volatile("cp.async.wait_group %0;" :: "n"(n) : "memory")

// fp32 pair -> half2 hi + half2 lo (residue)
__device__ __forceinline__ void hilo2(float x, float y, uint32_t& h, uint32_t& l) {
    __half2 hb = __floats2half2_rn(x, y);
    float2 f = __half22float2(hb);
    __half2 lb = __floats2half2_rn(x - f.x, y - f.y);
    h = *(uint32_t*)&hb;
    l = *(uint32_t*)&lb;
}

// fp32x8 -> fp16 HI-only 16-byte pack (proj A side truncates to hi)
__device__ __forceinline__ void cvt8h(float4 a, float4 b, uint4& hi) {
    __half2 h0 = __floats2half2_rn(a.x, a.y);
    __half2 h1 = __floats2half2_rn(a.z, a.w);
    __half2 h2 = __floats2half2_rn(b.x, b.y);
    __half2 h3 = __floats2half2_rn(b.z, b.w);
    hi.x = *(uint32_t*)&h0; hi.y = *(uint32_t*)&h1;
    hi.z = *(uint32_t*)&h2; hi.w = *(uint32_t*)&h3;
}

// ---------------------------------------------------------------------------
// W pre-split: all three weight matrices, fp32 -> fp16 hi/lo
// ---------------------------------------------------------------------------
__global__ void convW3(const float* __restrict__ W0, const float* __restrict__ W1,
                       const float* __restrict__ W2) {
    int i = blockIdx.x * 256 + threadIdx.x;
    const float* Ws[3] = { W0, W1, W2 };
    #pragma unroll
    for (int w = 0; w < 3; w++) {
        float x = Ws[w][i];
        __half h = __float2half_rn(x);
        g_Whi[w][i] = h;
        g_Wlo[w][i] = __float2half_rn(x - __half2float(h));
    }
}

// ---------------------------------------------------------------------------
// Projection GEMM (tensor pipe, fp16, 2-term: acc += Ah*(Bh+Bl)).
// All three projections in one launch (blockIdx.z).
// CTA = 128(M) x 128(N), K=256 in 4 chunks of BK=64 (halved sync count vs
// BK=32; same MMA order -> bit-identical result). Warp tile 64(M) x 32(N).
// 55KB dynamic smem -> 2 CTA/SM preserved (the verified overlap regime).
// ---------------------------------------------------------------------------
#define BK    64
#define TSTR  72                        // b16 stride per row (conflict-free)
#define PTILE_BYTES (128 * TSTR * 2)    // 18432 per tile
#define OFF_PAH 0
#define OFF_PBH PTILE_BYTES
#define OFF_PBL (2 * PTILE_BYTES)
#define PROJ_SMEM (3 * PTILE_BYTES)     // 55296 bytes

__global__ __launch_bounds__(256)
void proj_mma(const float* __restrict__ X0, const float* __restrict__ X1,
              const float* __restrict__ X2,
              const float* __restrict__ b0p, const float* __restrict__ b1p,
              const float* __restrict__ b2p)
{
    extern __shared__ __align__(16) char smc[];

    const int which = blockIdx.z;
    const float* X    = (which == 0) ? X0 : (which == 1) ? X1 : X2;
    const float* bias = (which == 0) ? b0p : (which == 1) ? b1p : b2p;
    __half* Ch = (which == 0) ? g_Qh : (which == 1) ? g_Kh : g_Vh;
    __half* Cl = (which == 0) ? g_Ql : (which == 1) ? g_Kl : g_Vl;
    const __half* Wh = g_Whi[which];
    const __half* Wl = g_Wlo[which];

    const int tid  = threadIdx.x;
    const int wid  = tid >> 5, lane = tid & 31;
    const int warpM = wid & 1, warpN = wid >> 1;       // 2(M) x 4(N) warp grid
    const int colBase = blockIdx.x * 128;
    const int rowBase = blockIdx.y * 128;

    const uint32_t sbase = smem_u32(smc);
    const uint32_t sAh = sbase + OFF_PAH;
    const uint32_t sBh = sbase + OFF_PBH, sBl = sbase + OFF_PBL;

    const int lrow = lane & 15, lkh = (lane >> 4) * 8;

    float acc[4][4][4];                  // [mt][n8][quad]
    #pragma unroll
    for (int i = 0; i < 4; i++)
        #pragma unroll
        for (int j = 0; j < 4; j++)
            #pragma unroll
            for (int q = 0; q < 4; q++) acc[i][j][q] = 0.f;

    for (int kc = 0; kc < DIM; kc += BK) {             // 4 chunks of 64
        // Stage B (pre-split W hi/lo): 128 n-rows x 8 segs of 8 fp16
        #pragma unroll
        for (int t = 0; t < 4; t++) {
            int idx = t * 256 + tid;                    // 0..1023
            int n = idx >> 3, seg = idx & 7;
            uint32_t soff = (uint32_t)(n * TSTR + seg * 8) * 2;
            const size_t go = (size_t)(colBase + n) * DIM + kc + seg * 8;
            cpasync16(sBh + soff, Wh + go);
            cpasync16(sBl + soff, Wl + go);
        }
        // Stage A (X tile, fp32 -> fp16 hi only): 128 rows x 8 segs of 8 floats
        #pragma unroll
        for (int t = 0; t < 4; t++) {
            int idx = t * 256 + tid;                    // 0..1023
            int row = idx >> 3, seg = idx & 7;
            const float4* p = (const float4*)(X + (size_t)(rowBase + row) * DIM
                                              + kc + seg * 8);
            float4 a = p[0], b = p[1];
            uint4 hi;
            cvt8h(a, b, hi);
            uint32_t soff = (uint32_t)(row * TSTR + seg * 8) * 2;
            *(uint4*)(smc + OFF_PAH + soff) = hi;
        }
        CP_COMMIT();
        CP_WAIT(0);
        __syncthreads();

        #pragma unroll
        for (int ks = 0; ks < 4; ks++) {                // four k16 steps
            const uint32_t kbyte = (uint32_t)(ks * 16 + lkh) * 2;

            // B fragments for this warp's 32 columns: 2 n16 tiles, hi+lo.
            uint32_t bh4[2][4], bl4[2][4];
            #pragma unroll
            for (int np = 0; np < 2; np++) {
                uint32_t ro = (uint32_t)((warpN * 32 + np * 16 + lrow) * TSTR) * 2;
                ldmx4(bh4[np], sBh + ro + kbyte);
                ldmx4(bl4[np], sBl + ro + kbyte);
            }
            // A hi fragment per m-tile; 8 MMAs each (B reused 4x).
            #pragma unroll
            for (int mt = 0; mt < 4; mt++) {
                uint32_t ahf[4];
                uint32_t ro = (uint32_t)((warpM * 64 + mt * 16 + lrow) * TSTR) * 2;
                ldmx4(ahf, sAh + ro + kbyte);
                #pragma unroll
                for (int np = 0; np < 2; np++) {
                    // n8 tile 2np uses {r0, r2}; 2np+1 uses {r1, r3}
                    mma16816(acc[mt][2 * np + 0], ahf, bh4[np][0], bh4[np][2]);
                    mma16816(acc[mt][2 * np + 1], ahf, bh4[np][1], bh4[np][3]);
                    mma16816(acc[mt][2 * np + 0], ahf, bl4[np][0], bl4[np][2]);
                    mma16816(acc[mt][2 * np + 1], ahf, bl4[np][1], bl4[np][3]);
                }
            }
        }
        __syncthreads();
    }

    // Epilogue: + bias, split to fp16 hi/lo, store as u32 (half2) pairs
    const int ccol0 = colBase + warpN * 32 + (lane & 3) * 2;
    #pragma unroll
    for (int nt = 0; nt < 4; nt++) {
        int col = ccol0 + nt * 8;
        float bb0 = bias[col], bb1 = bias[col + 1];
        #pragma unroll
        for (int mt = 0; mt < 4; mt++) {
            float* d = acc[mt][nt];
            int crow = rowBase + warpM * 64 + mt * 16 + (lane >> 2);
            size_t r0 = (size_t)crow * DIM + col;
            uint32_t h, l;
            hilo2(d[0] + bb0, d[1] + bb1, h, l);
            *(uint32_t*)&Ch[r0] = h;
            *(uint32_t*)&Cl[r0] = l;
            hilo2(d[2] + bb0, d[3] + bb1, h, l);
            *(uint32_t*)&Ch[r0 + 8 * DIM] = h;
            *(uint32_t*)&Cl[r0 + 8 * DIM] = l;
        }
    }
}

// ---------------------------------------------------------------------------
// Tensor-core block attention: one CTA per (b, s), 8 warps. (verified R7/R13
// structure; fp16 hi/lo inputs, 3-term MMA kept — precision budget is spent.)
// ---------------------------------------------------------------------------
#define AST 264                          // b16 row stride (conflict-free)
#define ATILE (64 * AST)                 // b16 elems per array
#define ASM_BYTES (6 * ATILE * 2)        // 202752 bytes

__global__ __launch_bounds__(256)
void attn_tc(float* __restrict__ outO, float* __restrict__ outW)
{
    extern __shared__ __half smb[];
    __half* aQh = smb;
    __half* aQl = smb + 1 * ATILE;
    __half* aKh = smb + 2 * ATILE;
    __half* aKl = smb + 3 * ATILE;
    __half* aVh = smb + 4 * ATILE;
    __half* aVl = smb + 5 * ATILE;

    const int bs  = blockIdx.x;
    const int tid = threadIdx.x;
    const size_t gbase = (size_t)bs * (NBLK * DIM);

    // ---- stage: 6 x (64 rows x 256 fp16) via cp.async ----
    {
        const __half* srcs[6] = { g_Qh + gbase, g_Ql + gbase,
                                  g_Kh + gbase, g_Kl + gbase,
                                  g_Vh + gbase, g_Vl + gbase };
        #pragma unroll
        for (int a = 0; a < 6; a++) {
            uint32_t sb = smem_u32(smb + a * ATILE);
            #pragma unroll
            for (int t = 0; t < 8; t++) {
                int idx = t * 256 + tid;
                int r = idx >> 5, gseg = idx & 31;
                cpasync16(sb + (uint32_t)(r * AST + gseg * 8) * 2,
                          srcs[a] + r * DIM + gseg * 8);
            }
        }
        CP_COMMIT();
        CP_WAIT(0);
        __syncthreads();
    }

    const uint32_t sQh = smem_u32(aQh), sQl = smem_u32(aQl);
    const uint32_t sKh = smem_u32(aKh), sKl = smem_u32(aKl);
    const uint32_t sVh = smem_u32(aVh), sVl = smem_u32(aVl);

    const int wid = tid >> 5, lane = tid & 31;
    const int g = lane >> 2, tq = lane & 3;
    const int b = bs >> 10, s0 = bs & 1023;
    const float scale = 0.17677669529663687f;   // 1/sqrt(32)

    #pragma unroll 1
    for (int pass = 0; pass < 2; pass++) {
        const int h = pass * 4 + (wid >> 1);
        const int rb = (wid & 1) * 32;
        const int hoff = h * DHD;

        // ---- Q A-fragments (hi & lo), 2 m-tiles x 2 k-blocks ----
        uint32_t qh[2][2][4], ql[2][2][4];
        #pragma unroll
        for (int mt = 0; mt < 2; mt++)
            #pragma unroll
            for (int kb = 0; kb < 2; kb++) {
                uint32_t ad = (uint32_t)((rb + 16 * mt + (lane & 15)) * AST
                              + hoff + 16 * kb + (lane >> 4) * 8) * 2;
                ldmx4(qh[mt][kb], sQh + ad);
                ldmx4(ql[mt][kb], sQl + ad);
            }

        // ---- scores S = Q K^T (hi/lo 3-MMA) ----
        float S[2][8][4];
        #pragma unroll
        for (int mt = 0; mt < 2; mt++)
            #pragma unroll
            for (int j = 0; j < 8; j++)
                #pragma unroll
                for (int q = 0; q < 4; q++) S[mt][j][q] = 0.f;

        #pragma unroll
        for (int jp = 0; jp < 4; jp++) {
            #pragma unroll
            for (int kb = 0; kb < 2; kb++) {
                uint32_t ad = (uint32_t)((16 * jp + (lane & 7) + ((lane >> 4) & 1) * 8) * AST
                              + hoff + 16 * kb + ((lane >> 3) & 1) * 8) * 2;
                uint32_t kh4[4], kl4[4];
                ldmx4(kh4, sKh + ad);
                ldmx4(kl4, sKl + ad);
                #pragma unroll
                for (int mt = 0; mt < 2; mt++) {
                    mma16816(S[mt][2 * jp + 0], qh[mt][kb], kh4[0], kh4[1]);
                    mma16816(S[mt][2 * jp + 0], qh[mt][kb], kl4[0], kl4[1]);
                    mma16816(S[mt][2 * jp + 0], ql[mt][kb], kh4[0], kh4[1]);
                    mma16816(S[mt][2 * jp + 1], qh[mt][kb], kh4[2], kh4[3]);
                    mma16816(S[mt][2 * jp + 1], qh[mt][kb], kl4[2], kl4[3]);
                    mma16816(S[mt][2 * jp + 1], ql[mt][kb], kh4[2], kh4[3]);
                }
            }
        }

        // ---- softmax in fragment registers + write attn_weight ----
        const size_t wb = (((size_t)b * NH + h) * SS + s0) * (NBLK * NBLK);
        #pragma unroll
        for (int mt = 0; mt < 2; mt++) {
            float m0 = -1e30f, m1 = -1e30f;
            #pragma unroll
            for (int j = 0; j < 8; j++) {
                #pragma unroll
                for (int q = 0; q < 4; q++) S[mt][j][q] *= scale;
                m0 = fmaxf(m0, fmaxf(S[mt][j][0], S[mt][j][1]));
                m1 = fmaxf(m1, fmaxf(S[mt][j][2], S[mt][j][3]));
            }
            m0 = fmaxf(m0, __shfl_xor_sync(0xffffffffu, m0, 1));
            m0 = fmaxf(m0, __shfl_xor_sync(0xffffffffu, m0, 2));
            m1 = fmaxf(m1, __shfl_xor_sync(0xffffffffu, m1, 1));
            m1 = fmaxf(m1, __shfl_xor_sync(0xffffffffu, m1, 2));
            float s0a = 0.f, s1a = 0.f;
            #pragma unroll
            for (int j = 0; j < 8; j++) {
                S[mt][j][0] = __expf(S[mt][j][0] - m0); s0a += S[mt][j][0];
                S[mt][j][1] = __expf(S[mt][j][1] - m0); s0a += S[mt][j][1];
                S[mt][j][2] = __expf(S[mt][j][2] - m1); s1a += S[mt][j][2];
                S[mt][j][3] = __expf(S[mt][j][3] - m1); s1a += S[mt][j][3];
            }
            s0a += __shfl_xor_sync(0xffffffffu, s0a, 1);
            s0a += __shfl_xor_sync(0xffffffffu, s0a, 2);
            s1a += __shfl_xor_sync(0xffffffffu, s1a, 1);
            s1a += __shfl_xor_sync(0xffffffffu, s1a, 2);
            float i0 = 1.0f / s0a, i1 = 1.0f / s1a;
            const int n0 = rb + 16 * mt + g;
            #pragma unroll
            for (int j = 0; j < 8; j++) {
                S[mt][j][0] *= i0; S[mt][j][1] *= i0;
                S[mt][j][2] *= i1; S[mt][j][3] *= i1;
                *(float2*)&outW[wb + (size_t)n0 * NBLK + 8 * j + 2 * tq] =
                    make_float2(S[mt][j][0], S[mt][j][1]);
                *(float2*)&outW[wb + (size_t)(n0 + 8) * NBLK + 8 * j + 2 * tq] =
                    make_float2(S[mt][j][2], S[mt][j][3]);
            }
        }

        // ---- PV: out = P V (hi/lo 3-MMA); P A-frags built from S regs ----
        float o[2][4][4];
        #pragma unroll
        for (int mt = 0; mt < 2; mt++)
            #pragma unroll
            for (int nd = 0; nd < 4; nd++)
                #pragma unroll
                for (int q = 0; q < 4; q++) o[mt][nd][q] = 0.f;

        #pragma unroll
        for (int kb2 = 0; kb2 < 4; kb2++) {
            uint32_t pah[2][4], pal[2][4];
            #pragma unroll
            for (int mt = 0; mt < 2; mt++) {
                const float* sa = S[mt][2 * kb2];
                const float* sb2 = S[mt][2 * kb2 + 1];
                hilo2(sa[0],  sa[1],  pah[mt][0], pal[mt][0]);
                hilo2(sa[2],  sa[3],  pah[mt][1], pal[mt][1]);
                hilo2(sb2[0], sb2[1], pah[mt][2], pal[mt][2]);
                hilo2(sb2[2], sb2[3], pah[mt][3], pal[mt][3]);
            }
            #pragma unroll
            for (int ndp = 0; ndp < 2; ndp++) {
                uint32_t ad = (uint32_t)((16 * kb2 + (lane & 7) + ((lane >> 3) & 1) * 8) * AST
                              + hoff + 16 * ndp + ((lane >> 4) & 1) * 8) * 2;
                uint32_t vh4[4], vl4[4];
                ldmx4t(vh4, sVh + ad);
                ldmx4t(vl4, sVl + ad);
                #pragma unroll
                for (int mt = 0; mt < 2; mt++) {
                    mma16816(o[mt][2 * ndp + 0], pah[mt], vh4[0], vh4[1]);
                    mma16816(o[mt][2 * ndp + 0], pah[mt], vl4[0], vl4[1]);
                    mma16816(o[mt][2 * ndp + 0], pal[mt], vh4[0], vh4[1]);
                    mma16816(o[mt][2 * ndp + 1], pah[mt], vh4[2], vh4[3]);
                    mma16816(o[mt][2 * ndp + 1], pah[mt], vl4[2], vl4[3]);
                    mma16816(o[mt][2 * ndp + 1], pal[mt], vh4[2], vh4[3]);
                }
            }
        }

        // ---- write attn_output ----
        #pragma unroll
        for (int mt = 0; mt < 2; mt++) {
            const int n0 = rb + 16 * mt + g;
            #pragma unroll
            for (int nd = 0; nd < 4; nd++) {
                const int cd = hoff + 8 * nd + 2 * tq;
                *(float2*)&outO[gbase + (size_t)n0 * DIM + cd] =
                    make_float2(o[mt][nd][0], o[mt][nd][1]);
                *(float2*)&outO[gbase + (size_t)(n0 + 8) * DIM + cd] =
                    make_float2(o[mt][nd][2], o[mt][nd][3]);
            }
        }
    }
}

// ---------------------------------------------------------------------------
// kernel_launch
// ---------------------------------------------------------------------------
extern "C" void kernel_launch(void* const* d_in, const int* in_sizes, int n_in,
                              void* d_out, int out_size)
{
    const float* query = (const float*)d_in[0];
    const float* key   = (const float*)d_in[1];
    const float* value = (const float*)d_in[2];
    const float* Wq    = (const float*)d_in[3];
    const float* bq    = (const float*)d_in[4];
    const float* Wk    = (const float*)d_in[5];
    const float* bk    = (const float*)d_in[6];
    const float* Wv    = (const float*)d_in[7];
    const float* bv    = (const float*)d_in[8];

    float* attn_out = (float*)d_out;
    float* attn_w   = (float*)d_out + (size_t)BB * SS * NBLK * DIM;

    cudaFuncSetAttribute(proj_mma, cudaFuncAttributeMaxDynamicSharedMemorySize,
                         PROJ_SMEM);
    cudaFuncSetAttribute(attn_tc, cudaFuncAttributeMaxDynamicSharedMemorySize,
                         ASM_BYTES);

    dim3 gg(DIM / 128, NROWS / 128, 3);   // all three projections, one launch
    convW3<<<256, 256>>>(Wq, Wk, Wv);
    proj_mma<<<gg, 256, PROJ_SMEM>>>(query, key, value, bq, bk, bv);

    attn_tc<<<BB * SS, 256, ASM_BYTES>>>(attn_out, attn_w);
}

// round 17
// speedup vs baseline: 1.1325x; 1.1325x over previous
#include <cuda_runtime.h>
#include <cuda_fp16.h>
#include <cstdint>

// Problem constants (fixed by the dataset)
#define BB    2
#define SS    1024
#define NBLK  64
#define DIM   256
#define NH    8
#define DHD   32
#define NROWS (BB * SS * NBLK)   // 131072

// ---------------------------------------------------------------------------
// Scratch (allocation-free rule: __device__ globals).
// Projected Q/K/V stored as fp16 hi/lo pairs.
// ---------------------------------------------------------------------------
__device__ __half g_Qh[NROWS * DIM];
__device__ __half g_Ql[NROWS * DIM];
__device__ __half g_Kh[NROWS * DIM];
__device__ __half g_Kl[NROWS * DIM];
__device__ __half g_Vh[NROWS * DIM];
__device__ __half g_Vl[NROWS * DIM];
__device__ __half g_Whi[3][DIM * DIM];
__device__ __half g_Wlo[3][DIM * DIM];

// ---------------------------------------------------------------------------
// Helpers
// ---------------------------------------------------------------------------
__device__ __forceinline__ uint32_t smem_u32(const void* p) {
    uint32_t a;
    asm("{ .reg .u64 t; cvta.to.shared.u64 t, %1; cvt.u32.u64 %0, t; }"
        : "=r"(a) : "l"(p));
    return a;
}
__device__ __forceinline__ void ldmx4(uint32_t* r, uint32_t addr) {
    asm volatile("ldmatrix.sync.aligned.m8n8.x4.shared.b16 {%0,%1,%2,%3}, [%4];"
                 : "=r"(r[0]), "=r"(r[1]), "=r"(r[2]), "=r"(r[3]) : "r"(addr));
}
__device__ __forceinline__ void ldmx4t(uint32_t* r, uint32_t addr) {
    asm volatile("ldmatrix.sync.aligned.m8n8.x4.trans.shared.b16 {%0,%1,%2,%3}, [%4];"
                 : "=r"(r[0]), "=r"(r[1]), "=r"(r[2]), "=r"(r[3]) : "r"(addr));
}
// fp16 MMA, fp32 accumulate
__device__ __forceinline__ void mma16816(float* d, const uint32_t* a,
                                         uint32_t b0, uint32_t b1) {
    asm volatile("mma.sync.aligned.m16n8k16.row.col.f32.f16.f16.f32 "
                 "{%0,%1,%2,%3}, {%4,%5,%6,%7}, {%8,%9}, {%0,%1,%2,%3};"
                 : "+f"(d[0]), "+f"(d[1]), "+f"(d[2]), "+f"(d[3])
                 : "r"(a[0]), "r"(a[1]), "r"(a[2]), "r"(a[3]), "r"(b0), "r"(b1));
}
__device__ __forceinline__ void cpasync16(uint32_t saddr, const void* gptr) {
    asm volatile("cp.async.cg.shared.global [%0], [%1], 16;"
                 :: "r"(saddr), "l"(gptr) : "memory");
}
#define CP_COMMIT() asm volatile("cp.async.commit_group;" ::: "memory")
#define CP_WAIT(n)  asm volatile("cp.async.wait_group %0;" :: "n"(n) : "memory")

// fp32 pair -> half2 hi + half2 lo (residue)
__device__ __forceinline__ void hilo2(float x, float y, uint32_t& h, uint32_t& l) {
    __half2 hb = __floats2half2_rn(x, y);
    float2 f = __half22float2(hb);
    __half2 lb = __floats2half2_rn(x - f.x, y - f.y);
    h = *(uint32_t*)&hb;
    l = *(uint32_t*)&lb;
}

// fp32x8 -> fp16 HI-only 16-byte pack (proj A side truncates to hi)
__device__ __forceinline__ void cvt8h(float4 a, float4 b, uint4& hi) {
    __half2 h0 = __floats2half2_rn(a.x, a.y);
    __half2 h1 = __floats2half2_rn(a.z, a.w);
    __half2 h2 = __floats2half2_rn(b.x, b.y);
    __half2 h3 = __floats2half2_rn(b.z, b.w);
    hi.x = *(uint32_t*)&h0; hi.y = *(uint32_t*)&h1;
    hi.z = *(uint32_t*)&h2; hi.w = *(uint32_t*)&h3;
}

// ---------------------------------------------------------------------------
// W pre-split: all three weight matrices, fp32 -> fp16 hi/lo
// ---------------------------------------------------------------------------
__global__ void convW3(const float* __restrict__ W0, const float* __restrict__ W1,
                       const float* __restrict__ W2) {
    int i = blockIdx.x * 256 + threadIdx.x;
    const float* Ws[3] = { W0, W1, W2 };
    #pragma unroll
    for (int w = 0; w < 3; w++) {
        float x = Ws[w][i];
        __half h = __float2half_rn(x);
        g_Whi[w][i] = h;
        g_Wlo[w][i] = __float2half_rn(x - __half2float(h));
    }
}

// ---------------------------------------------------------------------------
// Projection GEMM (R15-verified: fp16 2-term acc += Ah*(Bh+Bl), BK=32,
// 30KB static smem, 2 CTA/SM). All three projections in one launch (z).
// CTA = 128(M) x 128(N); warp tile 64(M) x 32(N).
// ---------------------------------------------------------------------------
#define BK    32
#define TSTR  40                        // b16 stride per row
#define TILE_B16 (128 * TSTR)           // 10240 bytes per tile

__global__ __launch_bounds__(256)
void proj_mma(const float* __restrict__ X0, const float* __restrict__ X1,
              const float* __restrict__ X2,
              const float* __restrict__ b0p, const float* __restrict__ b1p,
              const float* __restrict__ b2p)
{
    __shared__ __align__(16) __half Ah[TILE_B16];
    __shared__ __align__(16) __half Bh[TILE_B16];
    __shared__ __align__(16) __half Bl[TILE_B16];

    const int which = blockIdx.z;
    const float* X    = (which == 0) ? X0 : (which == 1) ? X1 : X2;
    const float* bias = (which == 0) ? b0p : (which == 1) ? b1p : b2p;
    __half* Ch = (which == 0) ? g_Qh : (which == 1) ? g_Kh : g_Vh;
    __half* Cl = (which == 0) ? g_Ql : (which == 1) ? g_Kl : g_Vl;
    const __half* Wh = g_Whi[which];
    const __half* Wl = g_Wlo[which];

    const int tid  = threadIdx.x;
    const int wid  = tid >> 5, lane = tid & 31;
    const int warpM = wid & 1, warpN = wid >> 1;       // 2(M) x 4(N) warp grid
    const int colBase = blockIdx.x * 128;
    const int rowBase = blockIdx.y * 128;

    const uint32_t sAh = smem_u32(Ah);
    const uint32_t sBh = smem_u32(Bh), sBl = smem_u32(Bl);

    const int lrow = lane & 15, lkh = (lane >> 4) * 8;

    float acc[4][4][4];                  // [mt][n8][quad]
    #pragma unroll
    for (int i = 0; i < 4; i++)
        #pragma unroll
        for (int j = 0; j < 4; j++)
            #pragma unroll
            for (int q = 0; q < 4; q++) acc[i][j][q] = 0.f;

    const int arow = tid >> 1, aseg0 = tid & 1;

    for (int kc = 0; kc < DIM; kc += BK) {
        // Stage B (pre-split W hi/lo) via cp.async
        #pragma unroll
        for (int t = 0; t < 2; t++) {
            int idx = t * 256 + tid;                    // 0..511
            int n = idx >> 2, seg = idx & 3;            // 8 fp16 per seg
            uint32_t soff = (uint32_t)(n * TSTR + seg * 8) * 2;
            const size_t go = (size_t)(colBase + n) * DIM + kc + seg * 8;
            cpasync16(sBh + soff, Wh + go);
            cpasync16(sBl + soff, Wl + go);
        }
        // Stage A (X tile, fp32 -> fp16 hi only)
        #pragma unroll
        for (int t = 0; t < 2; t++) {
            int seg = aseg0 + 2 * t;                    // 0..3
            const float4* p = (const float4*)(X + (size_t)(rowBase + arow) * DIM
                                              + kc + seg * 8);
            float4 a = p[0], b = p[1];
            uint4 hi;
            cvt8h(a, b, hi);
            uint32_t soff = (uint32_t)(arow * TSTR + seg * 8) * 2;
            *(uint4*)((char*)Ah + soff) = hi;
        }
        CP_COMMIT();
        CP_WAIT(0);
        __syncthreads();

        #pragma unroll
        for (int ks = 0; ks < 2; ks++) {                // two k16 steps
            const uint32_t kbyte = (uint32_t)(ks * 16 + lkh) * 2;

            // B fragments for this warp's 32 columns: 2 n16 tiles, hi+lo.
            uint32_t bh4[2][4], bl4[2][4];
            #pragma unroll
            for (int np = 0; np < 2; np++) {
                uint32_t ro = (uint32_t)((warpN * 32 + np * 16 + lrow) * TSTR) * 2;
                ldmx4(bh4[np], sBh + ro + kbyte);
                ldmx4(bl4[np], sBl + ro + kbyte);
            }
            // A hi fragment per m-tile; 8 MMAs each (B reused 4x).
            #pragma unroll
            for (int mt = 0; mt < 4; mt++) {
                uint32_t ahf[4];
                uint32_t ro = (uint32_t)((warpM * 64 + mt * 16 + lrow) * TSTR) * 2;
                ldmx4(ahf, sAh + ro + kbyte);
                #pragma unroll
                for (int np = 0; np < 2; np++) {
                    // n8 tile 2np uses {r0, r2}; 2np+1 uses {r1, r3}
                    mma16816(acc[mt][2 * np + 0], ahf, bh4[np][0], bh4[np][2]);
                    mma16816(acc[mt][2 * np + 1], ahf, bh4[np][1], bh4[np][3]);
                    mma16816(acc[mt][2 * np + 0], ahf, bl4[np][0], bl4[np][2]);
                    mma16816(acc[mt][2 * np + 1], ahf, bl4[np][1], bl4[np][3]);
                }
            }
        }
        __syncthreads();
    }

    // Epilogue: + bias, split to fp16 hi/lo, store as u32 (half2) pairs
    const int ccol0 = colBase + warpN * 32 + (lane & 3) * 2;
    #pragma unroll
    for (int nt = 0; nt < 4; nt++) {
        int col = ccol0 + nt * 8;
        float bb0 = bias[col], bb1 = bias[col + 1];
        #pragma unroll
        for (int mt = 0; mt < 4; mt++) {
            float* d = acc[mt][nt];
            int crow = rowBase + warpM * 64 + mt * 16 + (lane >> 2);
            size_t r0 = (size_t)crow * DIM + col;
            uint32_t h, l;
            hilo2(d[0] + bb0, d[1] + bb1, h, l);
            *(uint32_t*)&Ch[r0] = h;
            *(uint32_t*)&Cl[r0] = l;
            hilo2(d[2] + bb0, d[3] + bb1, h, l);
            *(uint32_t*)&Ch[r0 + 8 * DIM] = h;
            *(uint32_t*)&Cl[r0 + 8 * DIM] = l;
        }
    }
}

// ---------------------------------------------------------------------------
// Tensor-core block attention, HEAD-SPLIT: grid (2048, 2). Each CTA handles
// one (b,s) and a 4-head group, staging only its 128 columns of Q/K/V hi/lo
// -> 104KB smem -> 2 CTA/SM (staging of one CTA overlaps compute of the
// other). Per-head MMA order identical to R15 -> bit-identical results.
// ---------------------------------------------------------------------------
#define AST2 136                         // b16 row stride (conflict-free)
#define ATILE2 (64 * AST2)               // 8704 b16 per array
#define ASM_BYTES (6 * ATILE2 * 2)       // 104448 bytes

__global__ __launch_bounds__(256)
void attn_tc(float* __restrict__ outO, float* __restrict__ outW)
{
    extern __shared__ __half smb[];
    __half* aQh = smb;
    __half* aQl = smb + 1 * ATILE2;
    __half* aKh = smb + 2 * ATILE2;
    __half* aKl = smb + 3 * ATILE2;
    __half* aVh = smb + 4 * ATILE2;
    __half* aVl = smb + 5 * ATILE2;

    const int bs   = blockIdx.x;
    const int hgrp = blockIdx.y;                   // head group: 0 or 1
    const int tid  = threadIdx.x;
    const size_t gbase = (size_t)bs * (NBLK * DIM);
    const int colg = hgrp * 128;                   // global column base

    // ---- stage: 6 x (64 rows x 128 fp16) via cp.async ----
    {
        const __half* srcs[6] = { g_Qh + gbase, g_Ql + gbase,
                                  g_Kh + gbase, g_Kl + gbase,
                                  g_Vh + gbase, g_Vl + gbase };
        #pragma unroll
        for (int a = 0; a < 6; a++) {
            uint32_t sb = smem_u32(smb + a * ATILE2);
            #pragma unroll
            for (int t = 0; t < 4; t++) {
                int idx = t * 256 + tid;           // 0..1023
                int r = idx >> 4, gseg = idx & 15; // 64 rows x 16 segs of 8
                cpasync16(sb + (uint32_t)(r * AST2 + gseg * 8) * 2,
                          srcs[a] + r * DIM + colg + gseg * 8);
            }
        }
        CP_COMMIT();
        CP_WAIT(0);
        __syncthreads();
    }

    const uint32_t sQh = smem_u32(aQh), sQl = smem_u32(aQl);
    const uint32_t sKh = smem_u32(aKh), sKl = smem_u32(aKl);
    const uint32_t sVh = smem_u32(aVh), sVl = smem_u32(aVl);

    const int wid = tid >> 5, lane = tid & 31;
    const int g = lane >> 2, tq = lane & 3;
    const int b = bs >> 10, s0 = bs & 1023;
    const float scale = 0.17677669529663687f;   // 1/sqrt(32)

    const int hl   = wid >> 1;                   // local head 0..3
    const int h    = hgrp * 4 + hl;              // global head
    const int rb   = (wid & 1) * 32;
    const int hoff = hl * DHD;                   // smem column offset
    const int hofg = h * DHD;                    // global column offset

    // ---- Q A-fragments (hi & lo), 2 m-tiles x 2 k-blocks ----
    uint32_t qh[2][2][4], ql[2][2][4];
    #pragma unroll
    for (int mt = 0; mt < 2; mt++)
        #pragma unroll
        for (int kb = 0; kb < 2; kb++) {
            uint32_t ad = (uint32_t)((rb + 16 * mt + (lane & 15)) * AST2
                          + hoff + 16 * kb + (lane >> 4) * 8) * 2;
            ldmx4(qh[mt][kb], sQh + ad);
            ldmx4(ql[mt][kb], sQl + ad);
        }

    // ---- scores S = Q K^T (hi/lo 3-MMA) ----
    float S[2][8][4];
    #pragma unroll
    for (int mt = 0; mt < 2; mt++)
        #pragma unroll
        for (int j = 0; j < 8; j++)
            #pragma unroll
            for (int q = 0; q < 4; q++) S[mt][j][q] = 0.f;

    #pragma unroll
    for (int jp = 0; jp < 4; jp++) {
        #pragma unroll
        for (int kb = 0; kb < 2; kb++) {
            uint32_t ad = (uint32_t)((16 * jp + (lane & 7) + ((lane >> 4) & 1) * 8) * AST2
                          + hoff + 16 * kb + ((lane >> 3) & 1) * 8) * 2;
            uint32_t kh4[4], kl4[4];
            ldmx4(kh4, sKh + ad);
            ldmx4(kl4, sKl + ad);
            #pragma unroll
            for (int mt = 0; mt < 2; mt++) {
                mma16816(S[mt][2 * jp + 0], qh[mt][kb], kh4[0], kh4[1]);
                mma16816(S[mt][2 * jp + 0], qh[mt][kb], kl4[0], kl4[1]);
                mma16816(S[mt][2 * jp + 0], ql[mt][kb], kh4[0], kh4[1]);
                mma16816(S[mt][2 * jp + 1], qh[mt][kb], kh4[2], kh4[3]);
                mma16816(S[mt][2 * jp + 1], qh[mt][kb], kl4[2], kl4[3]);
                mma16816(S[mt][2 * jp + 1], ql[mt][kb], kh4[2], kh4[3]);
            }
        }
    }

    // ---- softmax in fragment registers + write attn_weight ----
    const size_t wb = (((size_t)b * NH + h) * SS + s0) * (NBLK * NBLK);
    #pragma unroll
    for (int mt = 0; mt < 2; mt++) {
        float m0 = -1e30f, m1 = -1e30f;
        #pragma unroll
        for (int j = 0; j < 8; j++) {
            #pragma unroll
            for (int q = 0; q < 4; q++) S[mt][j][q] *= scale;
            m0 = fmaxf(m0, fmaxf(S[mt][j][0], S[mt][j][1]));
            m1 = fmaxf(m1, fmaxf(S[mt][j][2], S[mt][j][3]));
        }
        m0 = fmaxf(m0, __shfl_xor_sync(0xffffffffu, m0, 1));
        m0 = fmaxf(m0, __shfl_xor_sync(0xffffffffu, m0, 2));
        m1 = fmaxf(m1, __shfl_xor_sync(0xffffffffu, m1, 1));
        m1 = fmaxf(m1, __shfl_xor_sync(0xffffffffu, m1, 2));
        float s0a = 0.f, s1a = 0.f;
        #pragma unroll
        for (int j = 0; j < 8; j++) {
            S[mt][j][0] = __expf(S[mt][j][0] - m0); s0a += S[mt][j][0];
            S[mt][j][1] = __expf(S[mt][j][1] - m0); s0a += S[mt][j][1];
            S[mt][j][2] = __expf(S[mt][j][2] - m1); s1a += S[mt][j][2];
            S[mt][j][3] = __expf(S[mt][j][3] - m1); s1a += S[mt][j][3];
        }
        s0a += __shfl_xor_sync(0xffffffffu, s0a, 1);
        s0a += __shfl_xor_sync(0xffffffffu, s0a, 2);
        s1a += __shfl_xor_sync(0xffffffffu, s1a, 1);
        s1a += __shfl_xor_sync(0xffffffffu, s1a, 2);
        float i0 = 1.0f / s0a, i1 = 1.0f / s1a;
        const int n0 = rb + 16 * mt + g;
        #pragma unroll
        for (int j = 0; j < 8; j++) {
            S[mt][j][0] *= i0; S[mt][j][1] *= i0;
            S[mt][j][2] *= i1; S[mt][j][3] *= i1;
            *(float2*)&outW[wb + (size_t)n0 * NBLK + 8 * j + 2 * tq] =
                make_float2(S[mt][j][0], S[mt][j][1]);
            *(float2*)&outW[wb + (size_t)(n0 + 8) * NBLK + 8 * j + 2 * tq] =
                make_float2(S[mt][j][2], S[mt][j][3]);
        }
    }

    // ---- PV: out = P V (hi/lo 3-MMA); P A-frags built from S regs ----
    float o[2][4][4];
    #pragma unroll
    for (int mt = 0; mt < 2; mt++)
        #pragma unroll
        for (int nd = 0; nd < 4; nd++)
            #pragma unroll
            for (int q = 0; q < 4; q++) o[mt][nd][q] = 0.f;

    #pragma unroll
    for (int kb2 = 0; kb2 < 4; kb2++) {
        uint32_t pah[2][4], pal[2][4];
        #pragma unroll
        for (int mt = 0; mt < 2; mt++) {
            const float* sa = S[mt][2 * kb2];
            const float* sb2 = S[mt][2 * kb2 + 1];
            hilo2(sa[0],  sa[1],  pah[mt][0], pal[mt][0]);
            hilo2(sa[2],  sa[3],  pah[mt][1], pal[mt][1]);
            hilo2(sb2[0], sb2[1], pah[mt][2], pal[mt][2]);
            hilo2(sb2[2], sb2[3], pah[mt][3], pal[mt][3]);
        }
        #pragma unroll
        for (int ndp = 0; ndp < 2; ndp++) {
            uint32_t ad = (uint32_t)((16 * kb2 + (lane & 7) + ((lane >> 3) & 1) * 8) * AST2
                          + hoff + 16 * ndp + ((lane >> 4) & 1) * 8) * 2;
            uint32_t vh4[4], vl4[4];
            ldmx4t(vh4, sVh + ad);
            ldmx4t(vl4, sVl + ad);
            #pragma unroll
            for (int mt = 0; mt < 2; mt++) {
                mma16816(o[mt][2 * ndp + 0], pah[mt], vh4[0], vh4[1]);
                mma16816(o[mt][2 * ndp + 0], pah[mt], vl4[0], vl4[1]);
                mma16816(o[mt][2 * ndp + 0], pal[mt], vh4[0], vh4[1]);
                mma16816(o[mt][2 * ndp + 1], pah[mt], vh4[2], vh4[3]);
                mma16816(o[mt][2 * ndp + 1], pah[mt], vl4[2], vl4[3]);
                mma16816(o[mt][2 * ndp + 1], pal[mt], vh4[2], vh4[3]);
            }
        }
    }

    // ---- write attn_output ----
    #pragma unroll
    for (int mt = 0; mt < 2; mt++) {
        const int n0 = rb + 16 * mt + g;
        #pragma unroll
        for (int nd = 0; nd < 4; nd++) {
            const int cd = hofg + 8 * nd + 2 * tq;
            *(float2*)&outO[gbase + (size_t)n0 * DIM + cd] =
                make_float2(o[mt][nd][0], o[mt][nd][1]);
            *(float2*)&outO[gbase + (size_t)(n0 + 8) * DIM + cd] =
                make_float2(o[mt][nd][2], o[mt][nd][3]);
        }
    }
}

// ---------------------------------------------------------------------------
// kernel_launch
// ---------------------------------------------------------------------------
extern "C" void kernel_launch(void* const* d_in, const int* in_sizes, int n_in,
                              void* d_out, int out_size)
{
    const float* query = (const float*)d_in[0];
    const float* key   = (const float*)d_in[1];
    const float* value = (const float*)d_in[2];
    const float* Wq    = (const float*)d_in[3];
    const float* bq    = (const float*)d_in[4];
    const float* Wk    = (const float*)d_in[5];
    const float* bk    = (const float*)d_in[6];
    const float* Wv    = (const float*)d_in[7];
    const float* bv    = (const float*)d_in[8];

    float* attn_out = (float*)d_out;
    float* attn_w   = (float*)d_out + (size_t)BB * SS * NBLK * DIM;

    cudaFuncSetAttribute(attn_tc, cudaFuncAttributeMaxDynamicSharedMemorySize,
                         ASM_BYTES);

    dim3 gg(DIM / 128, NROWS / 128, 3);   // all three projections, one launch
    convW3<<<256, 256>>>(Wq, Wk, Wv);
    proj_mma<<<gg, 256>>>(query, key, value, bq, bk, bv);

    dim3 ag(BB * SS, 2);                  // (b,s) x head-group
    attn_tc<<<ag, 256, ASM_BYTES>>>(attn_out, attn_w);
}